// round 4
// baseline (speedup 1.0000x reference)
#include <cuda_runtime.h>

#define NB 4
#define DK 256
#define DV 516
#define HW 4096
#define LM 32
#define DS 4            // d-splits inside attn block

// temp = log2(32*64*64 + 64*64) / sqrt(256)
#define TEMP 1.06527463f

// Scratch (static device allocations only; no cudaMalloc anywhere)
__device__ float g_q[NB * DK * HW];      // 16 MB: q[b][d][hw], pre-scaled by TEMP
__device__ float g_attn[NB * LM * HW];   // 2 MB:  attn[b][m][hw]

// ---------------------------------------------------------------------------
// Kernel 1: q[b][d][hw] = TEMP * sum_c Q[c][d] * fc[b][c][hw]
// 128x128 block tile, BK=16, 256 threads, 8x8 register tile, double-buffered
// smem with register prefetch -> one __syncthreads per 16-deep k-tile.
// ---------------------------------------------------------------------------
__global__ __launch_bounds__(256) void qproj_kernel(
    const float* __restrict__ fc, const float* __restrict__ Qm) {
    __shared__ float As[2][16][128];   // [buf][c][d]
    __shared__ float Bs[2][16][128];   // [buf][c][hw]

    const int b   = blockIdx.z;
    const int d0  = blockIdx.y * 128;
    const int hw0 = blockIdx.x * 128;
    const int tid = threadIdx.x;
    const int tx  = tid & 15;        // hw tile coord (x8)
    const int ty  = tid >> 4;        // d  tile coord (x8)

    const float* fcb = fc + (size_t)b * DK * HW;

    const int lr = tid >> 5;          // 0..7  (row pair base; rows lr, lr+8)
    const int lc = (tid & 31) * 4;    // 0..124

    float acc[8][8];
#pragma unroll
    for (int i = 0; i < 8; i++)
#pragma unroll
        for (int j = 0; j < 8; j++) acc[i][j] = 0.0f;

    // preload k-tile 0
    float4 pa0 = *(const float4*)(Qm + (size_t)lr * DK + d0 + lc);
    float4 pa1 = *(const float4*)(Qm + (size_t)(lr + 8) * DK + d0 + lc);
    float4 pb0 = *(const float4*)(fcb + (size_t)lr * HW + hw0 + lc);
    float4 pb1 = *(const float4*)(fcb + (size_t)(lr + 8) * HW + hw0 + lc);
    *(float4*)&As[0][lr][lc]     = pa0;
    *(float4*)&As[0][lr + 8][lc] = pa1;
    *(float4*)&Bs[0][lr][lc]     = pb0;
    *(float4*)&Bs[0][lr + 8][lc] = pb1;
    __syncthreads();

    int buf = 0;
    for (int k0 = 0; k0 < DK; k0 += 16) {
        const bool has_next = (k0 + 16) < DK;
        if (has_next) {
            pa0 = *(const float4*)(Qm + (size_t)(k0 + 16 + lr) * DK + d0 + lc);
            pa1 = *(const float4*)(Qm + (size_t)(k0 + 24 + lr) * DK + d0 + lc);
            pb0 = *(const float4*)(fcb + (size_t)(k0 + 16 + lr) * HW + hw0 + lc);
            pb1 = *(const float4*)(fcb + (size_t)(k0 + 24 + lr) * HW + hw0 + lc);
        }

#pragma unroll
        for (int k = 0; k < 16; k++) {
            float a[8], bb[8];
            *(float4*)(a)      = *(const float4*)&As[buf][k][ty * 8];
            *(float4*)(a + 4)  = *(const float4*)&As[buf][k][ty * 8 + 4];
            *(float4*)(bb)     = *(const float4*)&Bs[buf][k][tx * 8];
            *(float4*)(bb + 4) = *(const float4*)&Bs[buf][k][tx * 8 + 4];
#pragma unroll
            for (int i = 0; i < 8; i++)
#pragma unroll
                for (int j = 0; j < 8; j++) acc[i][j] += a[i] * bb[j];
        }

        if (has_next) {
            *(float4*)&As[buf ^ 1][lr][lc]     = pa0;
            *(float4*)&As[buf ^ 1][lr + 8][lc] = pa1;
            *(float4*)&Bs[buf ^ 1][lr][lc]     = pb0;
            *(float4*)&Bs[buf ^ 1][lr + 8][lc] = pb1;
            __syncthreads();
            buf ^= 1;
        }
    }

    float* qo = g_q + (size_t)b * DK * HW;
#pragma unroll
    for (int i = 0; i < 8; i++) {
        float* dst = qo + (size_t)(d0 + ty * 8 + i) * HW + hw0 + tx * 8;
        float4 v0, v1;
        v0.x = acc[i][0] * TEMP; v0.y = acc[i][1] * TEMP;
        v0.z = acc[i][2] * TEMP; v0.w = acc[i][3] * TEMP;
        v1.x = acc[i][4] * TEMP; v1.y = acc[i][5] * TEMP;
        v1.z = acc[i][6] * TEMP; v1.w = acc[i][7] * TEMP;
        *(float4*)(dst)     = v0;
        *(float4*)(dst + 4) = v1;
    }
}

// ---------------------------------------------------------------------------
// Kernel 2: scores + softmax fused.
// Block 512 = 32 hw lanes x 4 ms (8 m each) x 4 ds (64 d each). Each thread
// computes all 4 batches (key element loaded ONCE; full 128B coalesced loads).
// Partial scores reduced through 64KB dynamic smem; softmax by first 128 thr.
// ---------------------------------------------------------------------------
extern __shared__ float s_red[];   // [DS][LM][NB][32] = 64KB

__global__ __launch_bounds__(512) void attn_kernel(const float* __restrict__ key) {
    const int tid  = threadIdx.x;
    const int lane = tid & 31;           // hw
    const int ms   = (tid >> 5) & 3;     // m group (8 m)
    const int ds   = tid >> 7;           // d split (64 d)
    const int hw   = blockIdx.x * 32 + lane;

    const float* qp[NB];
#pragma unroll
    for (int b = 0; b < NB; b++)
        qp[b] = g_q + (size_t)b * DK * HW + (size_t)(ds * 64) * HW + hw;
    const float* kp[8];
#pragma unroll
    for (int j = 0; j < 8; j++)
        kp[j] = key + (size_t)(ms * 8 + j) * DK * HW + (size_t)(ds * 64) * HW + hw;

    float acc[NB][8];
#pragma unroll
    for (int b = 0; b < NB; b++)
#pragma unroll
        for (int j = 0; j < 8; j++) acc[b][j] = 0.0f;

#pragma unroll 4
    for (int d = 0; d < 64; d++) {
        float q0 = qp[0][0], q1 = qp[1][0], q2 = qp[2][0], q3 = qp[3][0];
#pragma unroll
        for (int j = 0; j < 8; j++) {
            const float kv = kp[j][0];
            acc[0][j] += q0 * kv;
            acc[1][j] += q1 * kv;
            acc[2][j] += q2 * kv;
            acc[3][j] += q3 * kv;
        }
#pragma unroll
        for (int b = 0; b < NB; b++) qp[b] += HW;
#pragma unroll
        for (int j = 0; j < 8; j++) kp[j] += HW;
    }

    // stash partials: s_red[ds][m][b][lane]
#pragma unroll
    for (int b = 0; b < NB; b++)
#pragma unroll
        for (int j = 0; j < 8; j++)
            s_red[(((ds * LM) + ms * 8 + j) * NB + b) * 32 + lane] = acc[b][j];
    __syncthreads();

    // softmax: 128 threads = 32 hw x 4 b
    if (tid < 128) {
        const int b = tid >> 5;
        const int l = tid & 31;
        const int hwg = blockIdx.x * 32 + l;
        float s[LM];
        float mx = -1e30f;
#pragma unroll
        for (int m = 0; m < LM; m++) {
            float v = s_red[((0 * LM + m) * NB + b) * 32 + l]
                    + s_red[((1 * LM + m) * NB + b) * 32 + l]
                    + s_red[((2 * LM + m) * NB + b) * 32 + l]
                    + s_red[((3 * LM + m) * NB + b) * 32 + l];
            s[m] = v;
            mx = fmaxf(mx, v);
        }
        float sum = 0.0f;
#pragma unroll
        for (int m = 0; m < LM; m++) { s[m] = __expf(s[m] - mx); sum += s[m]; }
        const float inv = 1.0f / sum;
        float* ap = g_attn + (size_t)b * LM * HW + hwg;
#pragma unroll
        for (int m = 0; m < LM; m++) ap[(size_t)m * HW] = s[m] * inv;
    }
}

// ---------------------------------------------------------------------------
// Kernel 3: out[b][c][hw] = fm[b][c][hw] + 0.5*sum_m attn[b][m][hw]*val[m][c][hw]
// hw vectorized x4 (LDG.128/STG.128). attn tile for all 4 batches staged in
// 64KB smem. Block 256 thr = 8 warps: warp&3 = batch, warp>>2 = c-half of a
// 43-wide c-chunk. One warp spans 128 hw (32 lanes x float4).
// Grid (32 hw-tiles, 12 c-chunks).
// ---------------------------------------------------------------------------
__global__ __launch_bounds__(256) void out_kernel(
    const float* __restrict__ fm, const float* __restrict__ val,
    float* __restrict__ out) {
    __shared__ float a_s[NB][LM][128];   // 64KB

    const int tid  = threadIdx.x;
    const int lane = tid & 31;
    const int wid  = tid >> 5;
    const int b    = wid & 3;
    const int ch   = wid >> 2;              // c-half: 0 -> 22 c's, 1 -> 21 c's
    const int hw0  = blockIdx.x * 128;
    const int c0   = blockIdx.y * 43;       // 516 = 12 * 43

    // stage attn tile: [4b][32m][128hw] — coalesced float4 fill
    {
        const float* gsrc = g_attn + hw0;
        // 4096 float4... total floats = 4*32*128 = 16384 -> 4096 float4, 16/thread
        for (int i = tid; i < NB * LM * 32; i += 256) {
            const int l4  = i & 31;            // float4 index within 128 hw
            const int m   = (i >> 5) & 31;
            const int bb  = i >> 10;
            *(float4*)&a_s[bb][m][l4 * 4] =
                *(const float4*)(gsrc + ((size_t)bb * LM + m) * HW + l4 * 4);
        }
    }
    __syncthreads();

    const int cbeg = c0 + (ch ? 22 : 0);
    const int cend = c0 + (ch ? 43 : 22);

    const float* fmp = fm + (size_t)b * DV * HW + hw0 + lane * 4;
    float*       op  = out + (size_t)b * DV * HW + hw0 + lane * 4;

    for (int c = cbeg; c < cend; c++) {
        const float* vp = val + (size_t)c * HW + hw0 + lane * 4;
        float4 acc = make_float4(0.f, 0.f, 0.f, 0.f);
#pragma unroll
        for (int m = 0; m < LM; m++) {
            const float4 v = *(const float4*)(vp + (size_t)m * DV * HW);
            const float4 a = *(const float4*)&a_s[b][m][lane * 4];
            acc.x += a.x * v.x;
            acc.y += a.y * v.y;
            acc.z += a.z * v.z;
            acc.w += a.w * v.w;
        }
        const float4 f = *(const float4*)(fmp + (size_t)c * HW);
        float4 o;
        o.x = f.x + 0.5f * acc.x;
        o.y = f.y + 0.5f * acc.y;
        o.z = f.z + 0.5f * acc.z;
        o.w = f.w + 0.5f * acc.w;
        *(float4*)(op + (size_t)c * HW) = o;
    }
}

// ---------------------------------------------------------------------------
// Launch. Inputs (metadata order): fc, fm, key_buffer, value_buffer, Q, K, V.
// concat(new, buffer)[-32:] keeps exactly the buffers -> K and V matrices are
// dead inputs; only q = fc@Q survives.
// ---------------------------------------------------------------------------
extern "C" void kernel_launch(void* const* d_in, const int* in_sizes, int n_in,
                              void* d_out, int out_size) {
    const float* fc   = (const float*)d_in[0];
    const float* fm   = (const float*)d_in[1];
    const float* keyb = (const float*)d_in[2];
    const float* valb = (const float*)d_in[3];
    const float* Qm   = (const float*)d_in[4];
    float* out = (float*)d_out;

    const int red_bytes = DS * LM * NB * 32 * sizeof(float);   // 64KB
    cudaFuncSetAttribute(attn_kernel,
                         cudaFuncAttributeMaxDynamicSharedMemorySize, red_bytes);

    qproj_kernel<<<dim3(HW / 128, DK / 128, NB), 256>>>(fc, Qm);
    attn_kernel<<<dim3(HW / 32), 512, red_bytes>>>(keyb);
    out_kernel<<<dim3(HW / 128, 12), 256>>>(fm, valb, out);
}

// round 5
// speedup vs baseline: 2.0684x; 2.0684x over previous
#include <cuda_runtime.h>

#define NB 4
#define DK 256
#define DV 516
#define HW 4096
#define LM 32
#define DS 4            // d-splits inside attn block
#define DQ 4            // d-splits across gridDim.y (64 d per block)

// temp = log2(32*64*64 + 64*64) / sqrt(256)
#define TEMP 1.06527463f

// Scratch (static device allocations only; no cudaMalloc anywhere)
__device__ float g_q[NB * DK * HW];            // 16 MB: q[b][d][hw], pre-scaled
__device__ float g_attn[NB * LM * HW];         // 2 MB:  attn[b][m][hw]
__device__ float g_part[DQ * NB * LM * HW];    // 8 MB:  partial scores

// ---------------------------------------------------------------------------
// Kernel 1: q[b][d][hw] = TEMP * sum_c Q[c][d] * fc[b][c][hw]
// 128x128 block tile, BK=8, 256 threads, 8x8 register tile, double-buffered
// smem with register prefetch -> one __syncthreads per k-tile. (R3 version.)
// ---------------------------------------------------------------------------
__global__ __launch_bounds__(256) void qproj_kernel(
    const float* __restrict__ fc, const float* __restrict__ Qm) {
    __shared__ float As[2][8][128];   // [buf][c][d]
    __shared__ float Bs[2][8][128];   // [buf][c][hw]

    const int b   = blockIdx.z;
    const int d0  = blockIdx.y * 128;
    const int hw0 = blockIdx.x * 128;
    const int tid = threadIdx.x;
    const int tx  = tid & 15;        // hw tile coord (x8)
    const int ty  = tid >> 4;        // d  tile coord (x8)

    const float* fcb = fc + (size_t)b * DK * HW;

    const int lr = tid >> 5;          // 0..7  (c within tile)
    const int lc = (tid & 31) * 4;    // 0..124

    float acc[8][8];
#pragma unroll
    for (int i = 0; i < 8; i++)
#pragma unroll
        for (int j = 0; j < 8; j++) acc[i][j] = 0.0f;

    float4 pa = *(const float4*)(Qm + (size_t)lr * DK + d0 + lc);
    float4 pb = *(const float4*)(fcb + (size_t)lr * HW + hw0 + lc);
    *(float4*)&As[0][lr][lc] = pa;
    *(float4*)&Bs[0][lr][lc] = pb;
    __syncthreads();

    int buf = 0;
    for (int k0 = 0; k0 < DK; k0 += 8) {
        const bool has_next = (k0 + 8) < DK;
        if (has_next) {
            pa = *(const float4*)(Qm + (size_t)(k0 + 8 + lr) * DK + d0 + lc);
            pb = *(const float4*)(fcb + (size_t)(k0 + 8 + lr) * HW + hw0 + lc);
        }

#pragma unroll
        for (int k = 0; k < 8; k++) {
            float a[8], bb[8];
            *(float4*)(a)      = *(const float4*)&As[buf][k][ty * 8];
            *(float4*)(a + 4)  = *(const float4*)&As[buf][k][ty * 8 + 4];
            *(float4*)(bb)     = *(const float4*)&Bs[buf][k][tx * 8];
            *(float4*)(bb + 4) = *(const float4*)&Bs[buf][k][tx * 8 + 4];
#pragma unroll
            for (int i = 0; i < 8; i++)
#pragma unroll
                for (int j = 0; j < 8; j++) acc[i][j] += a[i] * bb[j];
        }

        if (has_next) {
            *(float4*)&As[buf ^ 1][lr][lc] = pa;
            *(float4*)&Bs[buf ^ 1][lr][lc] = pb;
            __syncthreads();
            buf ^= 1;
        }
    }

    float* qo = g_q + (size_t)b * DK * HW;
#pragma unroll
    for (int i = 0; i < 8; i++) {
        float* dst = qo + (size_t)(d0 + ty * 8 + i) * HW + hw0 + tx * 8;
        float4 v0, v1;
        v0.x = acc[i][0] * TEMP; v0.y = acc[i][1] * TEMP;
        v0.z = acc[i][2] * TEMP; v0.w = acc[i][3] * TEMP;
        v1.x = acc[i][4] * TEMP; v1.y = acc[i][5] * TEMP;
        v1.z = acc[i][6] * TEMP; v1.w = acc[i][7] * TEMP;
        *(float4*)(dst)     = v0;
        *(float4*)(dst + 4) = v1;
    }
}

// ---------------------------------------------------------------------------
// Kernel 2a: partial scores. Grid (HW/32, DQ) = 512 blocks (full chip).
// Block 512 = 32 hw lanes x 4 ms (8 m each) x 4 ds (16 d each). Each thread
// computes all 4 batches (key element loaded ONCE; 128B coalesced loads).
// Block handles 64 d (= dq slice); internal 4-way ds reduced via 64KB smem;
// result -> g_part[dq][b][m][hw].
// ---------------------------------------------------------------------------
extern __shared__ float s_red[];   // [DS][LM][NB][32] = 64KB

__global__ __launch_bounds__(512) void attn_partial_kernel(
    const float* __restrict__ key) {
    const int tid  = threadIdx.x;
    const int lane = tid & 31;           // hw
    const int ms   = (tid >> 5) & 3;     // m group (8 m)
    const int ds   = tid >> 7;           // d sub-split (16 d each)
    const int hw   = blockIdx.x * 32 + lane;
    const int dq   = blockIdx.y;
    const int dbase = dq * 64 + ds * 16;

    const float* qp[NB];
#pragma unroll
    for (int b = 0; b < NB; b++)
        qp[b] = g_q + (size_t)b * DK * HW + (size_t)dbase * HW + hw;
    const float* kp[8];
#pragma unroll
    for (int j = 0; j < 8; j++)
        kp[j] = key + (size_t)(ms * 8 + j) * DK * HW + (size_t)dbase * HW + hw;

    float acc[NB][8];
#pragma unroll
    for (int b = 0; b < NB; b++)
#pragma unroll
        for (int j = 0; j < 8; j++) acc[b][j] = 0.0f;

#pragma unroll 2
    for (int d = 0; d < 16; d++) {
        float q0 = qp[0][0], q1 = qp[1][0], q2 = qp[2][0], q3 = qp[3][0];
#pragma unroll
        for (int j = 0; j < 8; j++) {
            const float kv = kp[j][0];
            acc[0][j] += q0 * kv;
            acc[1][j] += q1 * kv;
            acc[2][j] += q2 * kv;
            acc[3][j] += q3 * kv;
        }
#pragma unroll
        for (int b = 0; b < NB; b++) qp[b] += HW;
#pragma unroll
        for (int j = 0; j < 8; j++) kp[j] += HW;
    }

    // stash partials: s_red[ds][m][b][lane]
#pragma unroll
    for (int b = 0; b < NB; b++)
#pragma unroll
        for (int j = 0; j < 8; j++)
            s_red[(((ds * LM) + ms * 8 + j) * NB + b) * 32 + lane] = acc[b][j];
    __syncthreads();

    // reduce ds and write partial: 128 threads = 32 hw x 4 b
    if (tid < 128) {
        const int b   = tid >> 5;
        const int l   = tid & 31;
        const int hwg = blockIdx.x * 32 + l;
        float* pp = g_part + (((size_t)dq * NB + b) * LM) * HW + hwg;
#pragma unroll
        for (int m = 0; m < LM; m++) {
            const float v = s_red[((0 * LM + m) * NB + b) * 32 + l]
                          + s_red[((1 * LM + m) * NB + b) * 32 + l]
                          + s_red[((2 * LM + m) * NB + b) * 32 + l]
                          + s_red[((3 * LM + m) * NB + b) * 32 + l];
            pp[(size_t)m * HW] = v;
        }
    }
}

// ---------------------------------------------------------------------------
// Kernel 2b: finish — sum DQ partials, softmax over m, write g_attn.
// Block 128 = 32 hw x 4 b, grid 128. ~10MB traffic; ~5us.
// ---------------------------------------------------------------------------
__global__ __launch_bounds__(128) void attn_finish_kernel() {
    const int tid = threadIdx.x;
    const int b   = tid >> 5;
    const int l   = tid & 31;
    const int hw  = blockIdx.x * 32 + l;

    float s[LM];
    float mx = -1e30f;
#pragma unroll
    for (int m = 0; m < LM; m++) {
        float v = 0.0f;
#pragma unroll
        for (int dq = 0; dq < DQ; dq++)
            v += g_part[((((size_t)dq * NB + b) * LM) + m) * HW + hw];
        s[m] = v;
        mx = fmaxf(mx, v);
    }
    float sum = 0.0f;
#pragma unroll
    for (int m = 0; m < LM; m++) { s[m] = __expf(s[m] - mx); sum += s[m]; }
    const float inv = 1.0f / sum;
    float* ap = g_attn + (size_t)b * LM * HW + hw;
#pragma unroll
    for (int m = 0; m < LM; m++) ap[(size_t)m * HW] = s[m] * inv;
}

// ---------------------------------------------------------------------------
// Kernel 3: out[b][c][hw] = fm[b][c][hw] + 0.5*sum_m attn[b][m][hw]*val[m][c][hw]
// (Exact R3 version.) Block 256 = 32 hw x 2 batch-groups x 4 hw-subtiles.
// Each thread handles 2 batches (attn in 64 regs); val loaded once per pair.
// Grid (32 hw-tiles, 12 c-chunks of 43).
// ---------------------------------------------------------------------------
__global__ __launch_bounds__(256) void out_kernel(
    const float* __restrict__ fm, const float* __restrict__ val,
    float* __restrict__ out) {
    const int tid  = threadIdx.x;
    const int lane = tid & 31;
    const int bg   = (tid >> 5) & 1;
    const int sub  = tid >> 6;
    const int hw   = blockIdx.x * 128 + sub * 32 + lane;
    const int c0   = blockIdx.y * 43;       // 516 = 12 * 43
    const int b0   = bg * 2;
    const int b1   = b0 + 1;

    float a0[LM], a1[LM];
    {
        const float* ap0 = g_attn + (size_t)b0 * LM * HW + hw;
        const float* ap1 = g_attn + (size_t)b1 * LM * HW + hw;
#pragma unroll
        for (int m = 0; m < LM; m++) {
            a0[m] = ap0[(size_t)m * HW];
            a1[m] = ap1[(size_t)m * HW];
        }
    }

    const float* fmp0 = fm + (size_t)b0 * DV * HW + hw;
    const float* fmp1 = fm + (size_t)b1 * DV * HW + hw;
    float*       op0  = out + (size_t)b0 * DV * HW + hw;
    float*       op1  = out + (size_t)b1 * DV * HW + hw;

#pragma unroll 2
    for (int cc = 0; cc < 43; cc++) {
        const int c = c0 + cc;
        const float* vp = val + (size_t)c * HW + hw;
        float s0 = 0.0f, s1 = 0.0f, t0 = 0.0f, t1 = 0.0f;
#pragma unroll
        for (int m = 0; m < LM; m += 2) {
            const float v0 = vp[(size_t)(m * DV) * HW];
            const float v1 = vp[(size_t)((m + 1) * DV) * HW];
            s0 += a0[m] * v0;     t0 += a1[m] * v0;
            s1 += a0[m + 1] * v1; t1 += a1[m + 1] * v1;
        }
        op0[(size_t)c * HW] = fmp0[(size_t)c * HW] + 0.5f * (s0 + s1);
        op1[(size_t)c * HW] = fmp1[(size_t)c * HW] + 0.5f * (t0 + t1);
    }
}

// ---------------------------------------------------------------------------
// Launch. Inputs (metadata order): fc, fm, key_buffer, value_buffer, Q, K, V.
// concat(new, buffer)[-32:] keeps exactly the buffers -> K and V matrices are
// dead inputs; only q = fc@Q survives.
// ---------------------------------------------------------------------------
extern "C" void kernel_launch(void* const* d_in, const int* in_sizes, int n_in,
                              void* d_out, int out_size) {
    const float* fc   = (const float*)d_in[0];
    const float* fm   = (const float*)d_in[1];
    const float* keyb = (const float*)d_in[2];
    const float* valb = (const float*)d_in[3];
    const float* Qm   = (const float*)d_in[4];
    float* out = (float*)d_out;

    const int red_bytes = DS * LM * NB * 32 * sizeof(float);   // 64KB
    cudaFuncSetAttribute(attn_partial_kernel,
                         cudaFuncAttributeMaxDynamicSharedMemorySize, red_bytes);

    qproj_kernel<<<dim3(HW / 128, DK / 128, NB), 256>>>(fc, Qm);
    attn_partial_kernel<<<dim3(HW / 32, DQ), 512, red_bytes>>>(keyb);
    attn_finish_kernel<<<dim3(HW / 32), 128>>>();
    out_kernel<<<dim3(HW / 128, 12), 256>>>(fm, valb, out);
}